// round 12
// baseline (speedup 1.0000x reference)
#include <cuda_runtime.h>
#include <cuda_bf16.h>
#include <mma.h>
#include <cstdint>
#include <math.h>

using namespace nvcuda;

// Problem shape (fixed by the dataset)
constexpr int NB = 16384;   // batch rows
constexpr int ND = 2048;    // feature dim (K)
constexpr int NH = 512;     // hidden dim
constexpr int NSTAGE = ND / 32;   // 64 k-stages of BK=32

// Scratch (no cudaMalloc allowed)
__device__ float g_ypart[4 * NB];
__device__ float g_l1[NB];
__device__ __align__(128) __nv_bfloat16 g_w1t_hi[NH * ND];  // W1^T hi (bf16)
__device__ __align__(128) __nv_bfloat16 g_w1t_lo[NH * ND];  // W1^T residual (bf16)
__device__ __align__(128) __nv_bfloat16 g_x_hi[(size_t)NB * ND];
__device__ __align__(128) __nv_bfloat16 g_x_lo[(size_t)NB * ND];

// Dynamic SMEM. Tile = 128 rows x 40 halves (80B stride: 64B data + 16B pad).
// 80B stride => ldmatrix row starts hit banks (20r mod 32): all 8 rows disjoint
// => conflict-free LDSM (96B stride had a systematic 2-way conflict).
//   A(buf,split) at (buf*2+split)*10240, B(buf,split) at 40960 + (buf*2+split)*10240
// Epilogue aliases offset 0 as float ep[128][132] (67584 B < 81920).
constexpr int TILE_B = 10240;
constexpr int SMEM_DYN = 81920;

static __device__ __forceinline__ uint32_t smem_u32(const void* p) {
    uint32_t a;
    asm("{ .reg .u64 t; cvta.to.shared.u64 t, %1; cvt.u32.u64 %0, t; }" : "=r"(a) : "l"(p));
    return a;
}

// ============================================================================
// Kernel 0a: transpose + bf16-split W1[K,NH] -> W1T_hi/lo[NH,K]
// ============================================================================
__global__ void prep_w1t(const float* __restrict__ W1)
{
    __shared__ float t[32][33];
    const int k0 = blockIdx.x * 32, n0 = blockIdx.y * 32;
    const int tx = threadIdx.x, ty = threadIdx.y;   // 32 x 8
#pragma unroll
    for (int i = 0; i < 32; i += 8)
        t[ty + i][tx] = W1[(size_t)(k0 + ty + i) * NH + n0 + tx];
    __syncthreads();
#pragma unroll
    for (int i = 0; i < 32; i += 8) {
        float v = t[tx][ty + i];                    // W1[k0+tx][n0+ty+i]
        __nv_bfloat16 hi = __float2bfloat16(v);
        __nv_bfloat16 lo = __float2bfloat16(v - __bfloat162float(hi));
        g_w1t_hi[(size_t)(n0 + ty + i) * ND + k0 + tx] = hi;
        g_w1t_lo[(size_t)(n0 + ty + i) * ND + k0 + tx] = lo;
    }
}

// ============================================================================
// Kernel 0b: bf16-split x -> g_x_hi / g_x_lo  (memory-bound; 8 floats/thread)
// ============================================================================
__global__ void prep_x(const float* __restrict__ x)
{
    size_t i8 = (size_t)blockIdx.x * 256 + threadIdx.x;   // 8-float chunk index
    float4 v0 = ((const float4*)x)[2 * i8];
    float4 v1 = ((const float4*)x)[2 * i8 + 1];
    uint4 hi, lo;
    __nv_bfloat16 h[8], l[8];
    const float f[8] = {v0.x, v0.y, v0.z, v0.w, v1.x, v1.y, v1.z, v1.w};
#pragma unroll
    for (int i = 0; i < 8; i++) {
        h[i] = __float2bfloat16(f[i]);
        l[i] = __float2bfloat16(f[i] - __bfloat162float(h[i]));
    }
    hi.x = ((uint32_t)*(uint16_t*)&h[1] << 16) | *(uint16_t*)&h[0];
    hi.y = ((uint32_t)*(uint16_t*)&h[3] << 16) | *(uint16_t*)&h[2];
    hi.z = ((uint32_t)*(uint16_t*)&h[5] << 16) | *(uint16_t*)&h[4];
    hi.w = ((uint32_t)*(uint16_t*)&h[7] << 16) | *(uint16_t*)&h[6];
    lo.x = ((uint32_t)*(uint16_t*)&l[1] << 16) | *(uint16_t*)&l[0];
    lo.y = ((uint32_t)*(uint16_t*)&l[3] << 16) | *(uint16_t*)&l[2];
    lo.z = ((uint32_t)*(uint16_t*)&l[5] << 16) | *(uint16_t*)&l[4];
    lo.w = ((uint32_t)*(uint16_t*)&l[7] << 16) | *(uint16_t*)&l[6];
    ((uint4*)g_x_hi)[i8] = hi;
    ((uint4*)g_x_lo)[i8] = lo;
}

// ============================================================================
// Kernel 1: split-bf16 wmma GEMM  h = x @ W1  (3 MMAs per fp32 MMA) with fused
//           bias+ReLU+(.W2) epilogue -> g_ypart[nt][batch row].
// CTA: BM=128 batch x BN=128 hidden, BK=32, 8 warps (2m x 4n), warp m64n32.
// 2-stage cp.async pipeline, occ 2, conflict-free 80B smem stride.
// ============================================================================
__global__ __launch_bounds__(256, 2) void gemm_mma(
    const float* __restrict__ b1v, const float* __restrict__ W2v)
{
    extern __shared__ __align__(128) char smc[];
    __shared__ float b1s[128], w2s[128];
    __shared__ float red2[256];

    const int tid = threadIdx.x;
    const int wid = tid >> 5;
    const int nt = blockIdx.x;          // 0..3   hidden tile (fast -> x-slice L2 reuse)
    const int mt = blockIdx.y;          // 0..127 batch tile
    const int n0 = nt * 128;
    const int m0 = mt * 128;
    const int wm = wid & 1;             // warp m block (64)
    const int wn = wid >> 1;            // warp n block (32)
    const uint32_t smb = smem_u32(smc);

    if (tid < 128) { b1s[tid] = b1v[n0 + tid]; w2s[tid] = W2v[n0 + tid]; }

    wmma::fragment<wmma::accumulator, 16, 16, 16, float> acc[4][2];
#pragma unroll
    for (int i = 0; i < 4; i++)
#pragma unroll
        for (int j = 0; j < 2; j++) wmma::fill_fragment(acc[i][j], 0.0f);

    // ---- async stage loader: 2048 x 16B chunks per stage, 8 per thread ----
    auto issue = [&](int s) {
        const int buf = s & 1;
        const int k0 = s * 32;
#pragma unroll
        for (int i = 0; i < 8; i++) {
            int ch = tid + 256 * i;
            int isB = ch >> 10;
            int c2 = ch & 1023;
            int split = c2 >> 9;
            int rc = c2 & 511;
            int r = rc >> 2, q = rc & 3;
            const __nv_bfloat16* gbase =
                isB ? (split ? g_w1t_lo : g_w1t_hi) : (split ? g_x_lo : g_x_hi);
            int row0 = isB ? n0 : m0;
            const void* gptr = gbase + (size_t)(row0 + r) * ND + k0 + q * 8;
            uint32_t sptr = smb + (uint32_t)(isB * 40960 + (buf * 2 + split) * TILE_B
                                             + r * 80 + q * 16);
            asm volatile("cp.async.cg.shared.global [%0], [%1], 16;"
                         :: "r"(sptr), "l"(gptr));
        }
        asm volatile("cp.async.commit_group;");
    };

    issue(0);

    for (int s = 0; s < NSTAGE; s++) {
        const int buf = s & 1;
        if (s + 1 < NSTAGE) {
            issue(s + 1);
            asm volatile("cp.async.wait_group 1;");
        } else {
            asm volatile("cp.async.wait_group 0;");
        }
        __syncthreads();

        const __nv_bfloat16* Ah = (const __nv_bfloat16*)(smc + (buf * 2 + 0) * TILE_B);
        const __nv_bfloat16* Al = (const __nv_bfloat16*)(smc + (buf * 2 + 1) * TILE_B);
        const __nv_bfloat16* Bh = (const __nv_bfloat16*)(smc + 40960 + (buf * 2 + 0) * TILE_B);
        const __nv_bfloat16* Bl = (const __nv_bfloat16*)(smc + 40960 + (buf * 2 + 1) * TILE_B);

#pragma unroll
        for (int kk = 0; kk < 2; kk++) {
            wmma::fragment<wmma::matrix_b, 16, 16, 16, __nv_bfloat16, wmma::col_major> bh[2], bl[2];
#pragma unroll
            for (int j = 0; j < 2; j++) {
                wmma::load_matrix_sync(bh[j], Bh + (wn * 32 + 16 * j) * 40 + kk * 16, 40);
                wmma::load_matrix_sync(bl[j], Bl + (wn * 32 + 16 * j) * 40 + kk * 16, 40);
            }
#pragma unroll
            for (int i = 0; i < 4; i++) {
                wmma::fragment<wmma::matrix_a, 16, 16, 16, __nv_bfloat16, wmma::row_major> ah, al;
                wmma::load_matrix_sync(ah, Ah + (wm * 64 + 16 * i) * 40 + kk * 16, 40);
                wmma::load_matrix_sync(al, Al + (wm * 64 + 16 * i) * 40 + kk * 16, 40);
#pragma unroll
                for (int j = 0; j < 2; j++) {
                    wmma::mma_sync(acc[i][j], ah, bh[j], acc[i][j]);
                    wmma::mma_sync(acc[i][j], ah, bl[j], acc[i][j]);
                    wmma::mma_sync(acc[i][j], al, bh[j], acc[i][j]);
                }
            }
        }
        __syncthreads();
    }

    // ---- epilogue: h -> relu(h+b1)*W2, reduce over this CTA's 128 hidden cols
    float* ep = (float*)smc;   // [128][132], aliases stage buffers (loads done)
#pragma unroll
    for (int i = 0; i < 4; i++)
#pragma unroll
        for (int j = 0; j < 2; j++)
            wmma::store_matrix_sync(&ep[(size_t)(wm * 64 + 16 * i) * 132 + wn * 32 + 16 * j],
                                    acc[i][j], 132, wmma::mem_row_major);
    __syncthreads();

    const int row = tid & 127;
    const int half = tid >> 7;
    float p = 0.f;
#pragma unroll 8
    for (int n = half * 64; n < half * 64 + 64; n++)
        p += fmaxf(ep[(size_t)row * 132 + n] + b1s[n], 0.f) * w2s[n];
    red2[tid] = p;
    __syncthreads();
    if (tid < 128)
        g_ypart[(size_t)nt * NB + m0 + tid] = red2[tid] + red2[tid + 128];
}

// ============================================================================
// Kernel 2: fused predictor tail + exact per-row k-th-smallest |x| radix
// select + mask / sparse_x / actual_sparsity / l1. One 256t CTA per row.
// ============================================================================
__global__ __launch_bounds__(256) void select_mask(
    const float* __restrict__ x, const float* __restrict__ b2,
    float* __restrict__ out)
{
    __shared__ unsigned hist[2048];
    __shared__ unsigned buf[2048];
    __shared__ unsigned wsum[8];
    __shared__ float    fred[256];
    __shared__ unsigned sh_sel, sh_rem, sh_cnt, sh_thr, sh_k;

    const int t = threadIdx.x;
    const int lane = t & 31;
    const int warp = t >> 5;
    const int r = blockIdx.x;
    const float4* xrow = (const float4*)(x + (size_t)r * ND);

    // --- fused predictor tail (thread 0) ---
    if (t == 0) {
        float y = ((g_ypart[r] + g_ypart[NB + r])
                   + (g_ypart[2 * NB + r] + g_ypart[3 * NB + r])) + b2[0];
        float sig = 1.f / (1.f + expf(-y));
        float s = 0.05f + 0.25f * sig;
        out[(size_t)2 * NB * ND + r] = s;                 // sparsity
        float kf = rintf(2048.0f * (1.0f - s));           // half-even, matches jnp.round
        int k = (int)kf;
        if (k < 1) k = 1;
        sh_k = (unsigned)k;
        sh_cnt = 0u;
    }

    float4 xv0 = xrow[t];
    float4 xv1 = xrow[t + 256];
    unsigned u0[4], u1[4];
    u0[0] = __float_as_uint(xv0.x) & 0x7fffffffu;
    u0[1] = __float_as_uint(xv0.y) & 0x7fffffffu;
    u0[2] = __float_as_uint(xv0.z) & 0x7fffffffu;
    u0[3] = __float_as_uint(xv0.w) & 0x7fffffffu;
    u1[0] = __float_as_uint(xv1.x) & 0x7fffffffu;
    u1[1] = __float_as_uint(xv1.y) & 0x7fffffffu;
    u1[2] = __float_as_uint(xv1.z) & 0x7fffffffu;
    u1[3] = __float_as_uint(xv1.w) & 0x7fffffffu;
#pragma unroll
    for (int i = 0; i < 8; i++) hist[t + 256 * i] = 0u;
    __syncthreads();

#pragma unroll
    for (int i = 0; i < 4; i++) atomicAdd(&hist[u0[i] >> 20], 1u);
#pragma unroll
    for (int i = 0; i < 4; i++) atomicAdd(&hist[u1[i] >> 20], 1u);
    __syncthreads();

    const unsigned k = sh_k;

    // Shuffle-based segmented scan: thread t owns bins [8t, 8t+8)
    unsigned loc[8], ssum = 0u;
#pragma unroll
    for (int i = 0; i < 8; i++) { loc[i] = hist[8 * t + i]; ssum += loc[i]; }
    unsigned v = ssum;
#pragma unroll
    for (int off = 1; off < 32; off <<= 1) {
        unsigned n = __shfl_up_sync(0xffffffffu, v, off);
        if (lane >= off) v += n;
    }
    if (lane == 31) wsum[warp] = v;
    __syncthreads();
    unsigned wexcl = 0u;
#pragma unroll
    for (int w = 0; w < 8; w++) wexcl += (w < warp) ? wsum[w] : 0u;
    unsigned incl = wexcl + v;
    unsigned excl = incl - ssum;
    if (excl < k && k <= incl) {
        unsigned c = excl;
#pragma unroll
        for (int i = 0; i < 8; i++) {
            c += loc[i];
            if (c >= k) { sh_sel = 8 * t + i; sh_rem = k - (c - loc[i]); break; }
        }
    }
    __syncthreads();
    const unsigned sel = sh_sel;
    const unsigned rem = sh_rem;        // rank of threshold inside candidate bin
    const unsigned binexcl = k - rem;   // elements strictly below the bin

    // Warp-aggregated candidate compaction (buf order irrelevant for rank select)
    unsigned mv[8];
    unsigned nm = 0;
#pragma unroll
    for (int i = 0; i < 4; i++) if ((u0[i] >> 20) == sel) mv[nm++] = u0[i];
#pragma unroll
    for (int i = 0; i < 4; i++) if ((u1[i] >> 20) == sel) mv[nm++] = u1[i];
    unsigned v2 = nm;
#pragma unroll
    for (int off = 1; off < 32; off <<= 1) {
        unsigned n = __shfl_up_sync(0xffffffffu, v2, off);
        if (lane >= off) v2 += n;
    }
    unsigned wtot = __shfl_sync(0xffffffffu, v2, 31);
    unsigned wbase = 0;
    if (lane == 31 && wtot > 0) wbase = atomicAdd(&sh_cnt, wtot);
    wbase = __shfl_sync(0xffffffffu, wbase, 31);
    unsigned base = wbase + v2 - nm;
    for (unsigned j = 0; j < nm; j++) buf[base + j] = mv[j];
    __syncthreads();
    const int m = (int)sh_cnt;

    // Exact rank select among m candidates (rem-th smallest), tie-safe.
    // Winner also derives actual_sparsity: count_le = binexcl + less + eq.
    for (int c = t; c < m; c += 256) {
        unsigned vv = buf[c];
        unsigned less = 0u, eq = 0u;
        for (int j = 0; j < m; j++) {
            unsigned w = buf[j];
            less += (w < vv);
            eq   += (w == vv);
        }
        if (less < rem && rem <= less + eq) {
            sh_thr = vv;   // unique value among writers
            out[(size_t)2 * NB * ND + NB + r] =
                (float)(2048u - (binexcl + less + eq)) * (1.f / 2048.f);
        }
    }
    __syncthreads();
    const unsigned thr = sh_thr;   // exact bit pattern of sorted_abs[k-1]

    // Outputs: sparse_x, mask (strict > threshold), l1 (from abs bit patterns)
    float4* sp = (float4*)(out + (size_t)r * ND);
    float4* mk = (float4*)(out + (size_t)NB * ND + (size_t)r * ND);
    float l1 = 0.f;
    {
        float4 spv, mkv;
        bool k0b = u0[0] > thr, k1b = u0[1] > thr, k2b = u0[2] > thr, k3b = u0[3] > thr;
        spv.x = k0b ? xv0.x : 0.f; mkv.x = k0b ? 1.f : 0.f;
        spv.y = k1b ? xv0.y : 0.f; mkv.y = k1b ? 1.f : 0.f;
        spv.z = k2b ? xv0.z : 0.f; mkv.z = k2b ? 1.f : 0.f;
        spv.w = k3b ? xv0.w : 0.f; mkv.w = k3b ? 1.f : 0.f;
        l1 += __uint_as_float(k0b ? u0[0] : 0u) + __uint_as_float(k1b ? u0[1] : 0u)
            + __uint_as_float(k2b ? u0[2] : 0u) + __uint_as_float(k3b ? u0[3] : 0u);
        sp[t] = spv; mk[t] = mkv;

        k0b = u1[0] > thr; k1b = u1[1] > thr; k2b = u1[2] > thr; k3b = u1[3] > thr;
        spv.x = k0b ? xv1.x : 0.f; mkv.x = k0b ? 1.f : 0.f;
        spv.y = k1b ? xv1.y : 0.f; mkv.y = k1b ? 1.f : 0.f;
        spv.z = k2b ? xv1.z : 0.f; mkv.z = k2b ? 1.f : 0.f;
        spv.w = k3b ? xv1.w : 0.f; mkv.w = k3b ? 1.f : 0.f;
        l1 += __uint_as_float(k0b ? u1[0] : 0u) + __uint_as_float(k1b ? u1[1] : 0u)
            + __uint_as_float(k2b ? u1[2] : 0u) + __uint_as_float(k3b ? u1[3] : 0u);
        sp[t + 256] = spv; mk[t + 256] = mkv;
    }

    fred[t] = l1;
    __syncthreads();
    for (int off = 128; off > 0; off >>= 1) {
        if (t < off) fred[t] += fred[t + off];
        __syncthreads();
    }
    if (t == 0) g_l1[r] = fred[0];
}

// ============================================================================
// Kernel 3: deterministic mean of per-row l1 sums -> l1_reg scalar
// ============================================================================
__global__ void l1_reduce(float* __restrict__ out)
{
    __shared__ float sm[1024];
    int t = threadIdx.x;
    float s = 0.f;
    for (int i = t; i < NB; i += 1024) s += g_l1[i];
    sm[t] = s;
    __syncthreads();
    for (int off = 512; off > 0; off >>= 1) {
        if (t < off) sm[t] += sm[t + off];
        __syncthreads();
    }
    if (t == 0) out[(size_t)2 * NB * ND + 2 * NB] = sm[0] * (1.f / (float)NB);
}

// ============================================================================
extern "C" void kernel_launch(void* const* d_in, const int* in_sizes, int n_in,
                              void* d_out, int out_size)
{
    const float* x  = (const float*)d_in[0];
    const float* W1 = (const float*)d_in[1];
    const float* b1 = (const float*)d_in[2];
    const float* W2 = (const float*)d_in[3];
    const float* b2 = (const float*)d_in[4];
    float* out = (float*)d_out;

    cudaFuncSetAttribute(gemm_mma, cudaFuncAttributeMaxDynamicSharedMemorySize, SMEM_DYN);

    prep_w1t<<<dim3(ND / 32, NH / 32), dim3(32, 8)>>>(W1);
    prep_x<<<(int)((size_t)NB * ND / 8 / 256), 256>>>(x);
    gemm_mma<<<dim3(4, NB / 128), 256, SMEM_DYN>>>(b1, W2);
    select_mask<<<NB, 256>>>(x, b2, out);
    l1_reduce<<<1, 1024>>>(out);
}

// round 13
// speedup vs baseline: 1.0155x; 1.0155x over previous
#include <cuda_runtime.h>
#include <cuda_bf16.h>
#include <mma.h>
#include <cstdint>
#include <math.h>

using namespace nvcuda;

// Problem shape (fixed by the dataset)
constexpr int NB = 16384;   // batch rows
constexpr int ND = 2048;    // feature dim (K)
constexpr int NH = 512;     // hidden dim
constexpr int NSTAGE = ND / 32;   // 64 k-stages of BK=32

// Scratch (no cudaMalloc allowed)
__device__ float g_ypart[4 * NB];
__device__ float g_l1[NB];
__device__ __align__(128) __nv_bfloat16 g_w1t_hi[NH * ND];  // W1^T hi (bf16)
__device__ __align__(128) __nv_bfloat16 g_w1t_lo[NH * ND];  // W1^T residual (bf16)
__device__ __align__(128) __nv_bfloat16 g_x_hi[(size_t)NB * ND];
__device__ __align__(128) __nv_bfloat16 g_x_lo[(size_t)NB * ND];

// Dynamic SMEM (measured-best R10 layout): tile = 128 rows x 48 halves (96B
// stride: 64B data + 32B pad).
//   A(buf,split) at (buf*2+split)*12288, B(buf,split) at 49152 + (buf*2+split)*12288
// Epilogue aliases offset 0 as float ep[128][132] (67584 B).
constexpr int TILE_B = 12288;
constexpr int SMEM_DYN = 98304;

static __device__ __forceinline__ uint32_t smem_u32(const void* p) {
    uint32_t a;
    asm("{ .reg .u64 t; cvta.to.shared.u64 t, %1; cvt.u32.u64 %0, t; }" : "=r"(a) : "l"(p));
    return a;
}

// ============================================================================
// Kernel 0a: transpose + bf16-split W1[K,NH] -> W1T_hi/lo[NH,K]
// ============================================================================
__global__ void prep_w1t(const float* __restrict__ W1)
{
    __shared__ float t[32][33];
    const int k0 = blockIdx.x * 32, n0 = blockIdx.y * 32;
    const int tx = threadIdx.x, ty = threadIdx.y;   // 32 x 8
#pragma unroll
    for (int i = 0; i < 32; i += 8)
        t[ty + i][tx] = W1[(size_t)(k0 + ty + i) * NH + n0 + tx];
    __syncthreads();
#pragma unroll
    for (int i = 0; i < 32; i += 8) {
        float v = t[tx][ty + i];                    // W1[k0+tx][n0+ty+i]
        __nv_bfloat16 hi = __float2bfloat16(v);
        __nv_bfloat16 lo = __float2bfloat16(v - __bfloat162float(hi));
        g_w1t_hi[(size_t)(n0 + ty + i) * ND + k0 + tx] = hi;
        g_w1t_lo[(size_t)(n0 + ty + i) * ND + k0 + tx] = lo;
    }
}

// ============================================================================
// Kernel 0b: bf16-split x -> g_x_hi / g_x_lo  (memory-bound; 8 floats/thread)
// ============================================================================
__global__ void prep_x(const float* __restrict__ x)
{
    size_t i8 = (size_t)blockIdx.x * 256 + threadIdx.x;   // 8-float chunk index
    float4 v0 = ((const float4*)x)[2 * i8];
    float4 v1 = ((const float4*)x)[2 * i8 + 1];
    uint4 hi, lo;
    __nv_bfloat16 h[8], l[8];
    const float f[8] = {v0.x, v0.y, v0.z, v0.w, v1.x, v1.y, v1.z, v1.w};
#pragma unroll
    for (int i = 0; i < 8; i++) {
        h[i] = __float2bfloat16(f[i]);
        l[i] = __float2bfloat16(f[i] - __bfloat162float(h[i]));
    }
    hi.x = ((uint32_t)*(uint16_t*)&h[1] << 16) | *(uint16_t*)&h[0];
    hi.y = ((uint32_t)*(uint16_t*)&h[3] << 16) | *(uint16_t*)&h[2];
    hi.z = ((uint32_t)*(uint16_t*)&h[5] << 16) | *(uint16_t*)&h[4];
    hi.w = ((uint32_t)*(uint16_t*)&h[7] << 16) | *(uint16_t*)&h[6];
    lo.x = ((uint32_t)*(uint16_t*)&l[1] << 16) | *(uint16_t*)&l[0];
    lo.y = ((uint32_t)*(uint16_t*)&l[3] << 16) | *(uint16_t*)&l[2];
    lo.z = ((uint32_t)*(uint16_t*)&l[5] << 16) | *(uint16_t*)&l[4];
    lo.w = ((uint32_t)*(uint16_t*)&l[7] << 16) | *(uint16_t*)&l[6];
    ((uint4*)g_x_hi)[i8] = hi;
    ((uint4*)g_x_lo)[i8] = lo;
}

// ============================================================================
// Kernel 1: split-bf16 wmma GEMM  h = x @ W1  (3 MMAs per fp32 MMA) with fused
//           bias+ReLU+(.W2) epilogue -> g_ypart[nt][batch row].
// CTA: BM=128 batch x BN=128 hidden, BK=32, 8 warps (2m x 4n), warp m64n32.
// 2-stage cp.async pipeline, occ 2, ONE sync per stage:
//   wait(buf ready) -> sync -> issue(s+1) into buf^1 -> compute(buf).
// issue(s+1) is safe: buf^1 was last read in compute(s-1), and all warps
// passed this sync after finishing it.
// ============================================================================
__global__ __launch_bounds__(256, 2) void gemm_mma(
    const float* __restrict__ b1v, const float* __restrict__ W2v)
{
    extern __shared__ __align__(128) char smc[];
    __shared__ float b1s[128], w2s[128];
    __shared__ float red2[256];

    const int tid = threadIdx.x;
    const int wid = tid >> 5;
    const int nt = blockIdx.x;          // 0..3   hidden tile (fast -> x-slice L2 reuse)
    const int mt = blockIdx.y;          // 0..127 batch tile
    const int n0 = nt * 128;
    const int m0 = mt * 128;
    const int wm = wid & 1;             // warp m block (64)
    const int wn = wid >> 1;            // warp n block (32)
    const uint32_t smb = smem_u32(smc);

    if (tid < 128) { b1s[tid] = b1v[n0 + tid]; w2s[tid] = W2v[n0 + tid]; }

    wmma::fragment<wmma::accumulator, 16, 16, 16, float> acc[4][2];
#pragma unroll
    for (int i = 0; i < 4; i++)
#pragma unroll
        for (int j = 0; j < 2; j++) wmma::fill_fragment(acc[i][j], 0.0f);

    // ---- async stage loader: 2048 x 16B chunks per stage, 8 per thread ----
    auto issue = [&](int s) {
        const int buf = s & 1;
        const int k0 = s * 32;
#pragma unroll
        for (int i = 0; i < 8; i++) {
            int ch = tid + 256 * i;
            int isB = ch >> 10;
            int c2 = ch & 1023;
            int split = c2 >> 9;
            int rc = c2 & 511;
            int r = rc >> 2, q = rc & 3;
            const __nv_bfloat16* gbase =
                isB ? (split ? g_w1t_lo : g_w1t_hi) : (split ? g_x_lo : g_x_hi);
            int row0 = isB ? n0 : m0;
            const void* gptr = gbase + (size_t)(row0 + r) * ND + k0 + q * 8;
            uint32_t sptr = smb + (uint32_t)(isB * 49152 + (buf * 2 + split) * TILE_B
                                             + r * 96 + q * 16);
            asm volatile("cp.async.cg.shared.global [%0], [%1], 16;"
                         :: "r"(sptr), "l"(gptr));
        }
        asm volatile("cp.async.commit_group;");
    };

    issue(0);

    for (int s = 0; s < NSTAGE; s++) {
        const int buf = s & 1;
        asm volatile("cp.async.wait_group 0;");   // stage s data resident
        __syncthreads();                          // also: everyone done with buf^1
        if (s + 1 < NSTAGE) issue(s + 1);         // fill buf^1 under compute(s)

        const __nv_bfloat16* Ah = (const __nv_bfloat16*)(smc + (buf * 2 + 0) * TILE_B);
        const __nv_bfloat16* Al = (const __nv_bfloat16*)(smc + (buf * 2 + 1) * TILE_B);
        const __nv_bfloat16* Bh = (const __nv_bfloat16*)(smc + 49152 + (buf * 2 + 0) * TILE_B);
        const __nv_bfloat16* Bl = (const __nv_bfloat16*)(smc + 49152 + (buf * 2 + 1) * TILE_B);

#pragma unroll
        for (int kk = 0; kk < 2; kk++) {
            wmma::fragment<wmma::matrix_b, 16, 16, 16, __nv_bfloat16, wmma::col_major> bh[2], bl[2];
#pragma unroll
            for (int j = 0; j < 2; j++) {
                wmma::load_matrix_sync(bh[j], Bh + (wn * 32 + 16 * j) * 48 + kk * 16, 48);
                wmma::load_matrix_sync(bl[j], Bl + (wn * 32 + 16 * j) * 48 + kk * 16, 48);
            }
#pragma unroll
            for (int i = 0; i < 4; i++) {
                wmma::fragment<wmma::matrix_a, 16, 16, 16, __nv_bfloat16, wmma::row_major> ah, al;
                wmma::load_matrix_sync(ah, Ah + (wm * 64 + 16 * i) * 48 + kk * 16, 48);
                wmma::load_matrix_sync(al, Al + (wm * 64 + 16 * i) * 48 + kk * 16, 48);
#pragma unroll
                for (int j = 0; j < 2; j++) {
                    wmma::mma_sync(acc[i][j], ah, bh[j], acc[i][j]);
                    wmma::mma_sync(acc[i][j], ah, bl[j], acc[i][j]);
                    wmma::mma_sync(acc[i][j], al, bh[j], acc[i][j]);
                }
            }
        }
    }
    __syncthreads();   // all compute done before epilogue aliases the buffers

    // ---- epilogue: h -> relu(h+b1)*W2, reduce over this CTA's 128 hidden cols
    float* ep = (float*)smc;   // [128][132], aliases stage buffers
#pragma unroll
    for (int i = 0; i < 4; i++)
#pragma unroll
        for (int j = 0; j < 2; j++)
            wmma::store_matrix_sync(&ep[(size_t)(wm * 64 + 16 * i) * 132 + wn * 32 + 16 * j],
                                    acc[i][j], 132, wmma::mem_row_major);
    __syncthreads();

    const int row = tid & 127;
    const int half = tid >> 7;
    float p = 0.f;
#pragma unroll 8
    for (int n = half * 64; n < half * 64 + 64; n++)
        p += fmaxf(ep[(size_t)row * 132 + n] + b1s[n], 0.f) * w2s[n];
    red2[tid] = p;
    __syncthreads();
    if (tid < 128)
        g_ypart[(size_t)nt * NB + m0 + tid] = red2[tid] + red2[tid + 128];
}

// ============================================================================
// Kernel 2: fused predictor tail + exact per-row k-th-smallest |x| radix
// select + mask / sparse_x / actual_sparsity / l1. One 256t CTA per row.
// Occ 6 (reg-trimmed: scan keeps only per-thread sums; winner re-reads hist).
// ============================================================================
__global__ __launch_bounds__(256, 6) void select_mask(
    const float* __restrict__ x, const float* __restrict__ b2,
    float* __restrict__ out)
{
    __shared__ unsigned hist[2048];
    __shared__ unsigned buf[2048];
    __shared__ unsigned wsum[8];
    __shared__ float    fred[256];
    __shared__ unsigned sh_sel, sh_rem, sh_cnt, sh_thr, sh_k;

    const int t = threadIdx.x;
    const int lane = t & 31;
    const int warp = t >> 5;
    const int r = blockIdx.x;
    const float4* xrow = (const float4*)(x + (size_t)r * ND);

    // --- fused predictor tail (thread 0) ---
    if (t == 0) {
        float y = ((g_ypart[r] + g_ypart[NB + r])
                   + (g_ypart[2 * NB + r] + g_ypart[3 * NB + r])) + b2[0];
        float sig = 1.f / (1.f + expf(-y));
        float s = 0.05f + 0.25f * sig;
        out[(size_t)2 * NB * ND + r] = s;                 // sparsity
        float kf = rintf(2048.0f * (1.0f - s));           // half-even, matches jnp.round
        int k = (int)kf;
        if (k < 1) k = 1;
        sh_k = (unsigned)k;
        sh_cnt = 0u;
    }

    float4 xv0 = xrow[t];
    float4 xv1 = xrow[t + 256];
    unsigned u0[4], u1[4];
    u0[0] = __float_as_uint(xv0.x) & 0x7fffffffu;
    u0[1] = __float_as_uint(xv0.y) & 0x7fffffffu;
    u0[2] = __float_as_uint(xv0.z) & 0x7fffffffu;
    u0[3] = __float_as_uint(xv0.w) & 0x7fffffffu;
    u1[0] = __float_as_uint(xv1.x) & 0x7fffffffu;
    u1[1] = __float_as_uint(xv1.y) & 0x7fffffffu;
    u1[2] = __float_as_uint(xv1.z) & 0x7fffffffu;
    u1[3] = __float_as_uint(xv1.w) & 0x7fffffffu;
#pragma unroll
    for (int i = 0; i < 8; i++) hist[t + 256 * i] = 0u;
    __syncthreads();

#pragma unroll
    for (int i = 0; i < 4; i++) atomicAdd(&hist[u0[i] >> 20], 1u);
#pragma unroll
    for (int i = 0; i < 4; i++) atomicAdd(&hist[u1[i] >> 20], 1u);
    __syncthreads();

    const unsigned k = sh_k;

    // Shuffle-based segmented scan over bin sums; thread t owns bins [8t, 8t+8)
    unsigned ssum = 0u;
#pragma unroll
    for (int i = 0; i < 8; i++) ssum += hist[8 * t + i];
    unsigned v = ssum;
#pragma unroll
    for (int off = 1; off < 32; off <<= 1) {
        unsigned n = __shfl_up_sync(0xffffffffu, v, off);
        if (lane >= off) v += n;
    }
    if (lane == 31) wsum[warp] = v;
    __syncthreads();
    unsigned wexcl = 0u;
#pragma unroll
    for (int w = 0; w < 8; w++) wexcl += (w < warp) ? wsum[w] : 0u;
    unsigned incl = wexcl + v;
    unsigned excl = incl - ssum;
    if (excl < k && k <= incl) {
        unsigned c = excl;
        for (int i = 0; i < 8; i++) {       // winner re-reads its bins from smem
            unsigned hc = hist[8 * t + i];
            c += hc;
            if (c >= k) { sh_sel = 8 * t + i; sh_rem = k - (c - hc); break; }
        }
    }
    __syncthreads();
    const unsigned sel = sh_sel;
    const unsigned rem = sh_rem;        // rank of threshold inside candidate bin
    const unsigned binexcl = k - rem;   // elements strictly below the bin

    // Warp-aggregated candidate compaction (buf order irrelevant for rank select)
    unsigned mv[8];
    unsigned nm = 0;
#pragma unroll
    for (int i = 0; i < 4; i++) if ((u0[i] >> 20) == sel) mv[nm++] = u0[i];
#pragma unroll
    for (int i = 0; i < 4; i++) if ((u1[i] >> 20) == sel) mv[nm++] = u1[i];
    unsigned v2 = nm;
#pragma unroll
    for (int off = 1; off < 32; off <<= 1) {
        unsigned n = __shfl_up_sync(0xffffffffu, v2, off);
        if (lane >= off) v2 += n;
    }
    unsigned wtot = __shfl_sync(0xffffffffu, v2, 31);
    unsigned wbase = 0;
    if (lane == 31 && wtot > 0) wbase = atomicAdd(&sh_cnt, wtot);
    wbase = __shfl_sync(0xffffffffu, wbase, 31);
    unsigned base = wbase + v2 - nm;
    for (unsigned j = 0; j < nm; j++) buf[base + j] = mv[j];
    __syncthreads();
    const int m = (int)sh_cnt;

    // Exact rank select among m candidates (rem-th smallest), tie-safe.
    // Winner also derives actual_sparsity: count_le = binexcl + less + eq.
    for (int c = t; c < m; c += 256) {
        unsigned vv = buf[c];
        unsigned less = 0u, eq = 0u;
        for (int j = 0; j < m; j++) {
            unsigned w = buf[j];
            less += (w < vv);
            eq   += (w == vv);
        }
        if (less < rem && rem <= less + eq) {
            sh_thr = vv;   // unique value among writers
            out[(size_t)2 * NB * ND + NB + r] =
                (float)(2048u - (binexcl + less + eq)) * (1.f / 2048.f);
        }
    }
    __syncthreads();
    const unsigned thr = sh_thr;   // exact bit pattern of sorted_abs[k-1]

    // Outputs: sparse_x, mask (strict > threshold), l1 (from abs bit patterns)
    float4* sp = (float4*)(out + (size_t)r * ND);
    float4* mk = (float4*)(out + (size_t)NB * ND + (size_t)r * ND);
    float l1 = 0.f;
    {
        float4 spv, mkv;
        bool k0b = u0[0] > thr, k1b = u0[1] > thr, k2b = u0[2] > thr, k3b = u0[3] > thr;
        spv.x = k0b ? xv0.x : 0.f; mkv.x = k0b ? 1.f : 0.f;
        spv.y = k1b ? xv0.y : 0.f; mkv.y = k1b ? 1.f : 0.f;
        spv.z = k2b ? xv0.z : 0.f; mkv.z = k2b ? 1.f : 0.f;
        spv.w = k3b ? xv0.w : 0.f; mkv.w = k3b ? 1.f : 0.f;
        l1 += __uint_as_float(k0b ? u0[0] : 0u) + __uint_as_float(k1b ? u0[1] : 0u)
            + __uint_as_float(k2b ? u0[2] : 0u) + __uint_as_float(k3b ? u0[3] : 0u);
        sp[t] = spv; mk[t] = mkv;

        k0b = u1[0] > thr; k1b = u1[1] > thr; k2b = u1[2] > thr; k3b = u1[3] > thr;
        spv.x = k0b ? xv1.x : 0.f; mkv.x = k0b ? 1.f : 0.f;
        spv.y = k1b ? xv1.y : 0.f; mkv.y = k1b ? 1.f : 0.f;
        spv.z = k2b ? xv1.z : 0.f; mkv.z = k2b ? 1.f : 0.f;
        spv.w = k3b ? xv1.w : 0.f; mkv.w = k3b ? 1.f : 0.f;
        l1 += __uint_as_float(k0b ? u1[0] : 0u) + __uint_as_float(k1b ? u1[1] : 0u)
            + __uint_as_float(k2b ? u1[2] : 0u) + __uint_as_float(k3b ? u1[3] : 0u);
        sp[t + 256] = spv; mk[t + 256] = mkv;
    }

    fred[t] = l1;
    __syncthreads();
    for (int off = 128; off > 0; off >>= 1) {
        if (t < off) fred[t] += fred[t + off];
        __syncthreads();
    }
    if (t == 0) g_l1[r] = fred[0];
}

// ============================================================================
// Kernel 3: deterministic mean of per-row l1 sums -> l1_reg scalar
// ============================================================================
__global__ void l1_reduce(float* __restrict__ out)
{
    __shared__ float sm[1024];
    int t = threadIdx.x;
    float s = 0.f;
    for (int i = t; i < NB; i += 1024) s += g_l1[i];
    sm[t] = s;
    __syncthreads();
    for (int off = 512; off > 0; off >>= 1) {
        if (t < off) sm[t] += sm[t + off];
        __syncthreads();
    }
    if (t == 0) out[(size_t)2 * NB * ND + 2 * NB] = sm[0] * (1.f / (float)NB);
}

// ============================================================================
extern "C" void kernel_launch(void* const* d_in, const int* in_sizes, int n_in,
                              void* d_out, int out_size)
{
    const float* x  = (const float*)d_in[0];
    const float* W1 = (const float*)d_in[1];
    const float* b1 = (const float*)d_in[2];
    const float* W2 = (const float*)d_in[3];
    const float* b2 = (const float*)d_in[4];
    float* out = (float*)d_out;

    cudaFuncSetAttribute(gemm_mma, cudaFuncAttributeMaxDynamicSharedMemorySize, SMEM_DYN);

    prep_w1t<<<dim3(ND / 32, NH / 32), dim3(32, 8)>>>(W1);
    prep_x<<<(int)((size_t)NB * ND / 8 / 256), 256>>>(x);
    gemm_mma<<<dim3(4, NB / 128), 256, SMEM_DYN>>>(b1, W2);
    select_mask<<<NB, 256>>>(x, b2, out);
    l1_reduce<<<1, 1024>>>(out);
}

// round 14
// speedup vs baseline: 1.0473x; 1.0313x over previous
#include <cuda_runtime.h>
#include <cuda_bf16.h>
#include <mma.h>
#include <cstdint>
#include <math.h>

using namespace nvcuda;

// Problem shape (fixed by the dataset)
constexpr int NB = 16384;   // batch rows
constexpr int ND = 2048;    // feature dim (K)
constexpr int NH = 512;     // hidden dim
constexpr int NSTAGE = ND / 32;   // 64 k-stages of BK=32

// Scratch (no cudaMalloc allowed)
__device__ float g_ypart[4 * NB];
__device__ float g_l1[NB];
__device__ __align__(128) __nv_bfloat16 g_w1t_hi[NH * ND];  // W1^T hi (bf16)
__device__ __align__(128) __nv_bfloat16 g_w1t_lo[NH * ND];  // W1^T residual (bf16)
__device__ __align__(128) __nv_bfloat16 g_x_hi[(size_t)NB * ND];
__device__ __align__(128) __nv_bfloat16 g_x_lo[(size_t)NB * ND];

// Dynamic SMEM (measured-best R10 layout): tile = 128 rows x 48 halves (96B
// stride: 64B data + 32B pad).
//   A(buf,split) at (buf*2+split)*12288, B(buf,split) at 49152 + (buf*2+split)*12288
// Epilogue aliases offset 0 as float ep[128][132] (67584 B).
constexpr int TILE_B = 12288;
constexpr int SMEM_DYN = 98304;

static __device__ __forceinline__ uint32_t smem_u32(const void* p) {
    uint32_t a;
    asm("{ .reg .u64 t; cvta.to.shared.u64 t, %1; cvt.u32.u64 %0, t; }" : "=r"(a) : "l"(p));
    return a;
}

// ============================================================================
// Kernel 0a: transpose + bf16-split W1[K,NH] -> W1T_hi/lo[NH,K]
// ============================================================================
__global__ void prep_w1t(const float* __restrict__ W1)
{
    __shared__ float t[32][33];
    const int k0 = blockIdx.x * 32, n0 = blockIdx.y * 32;
    const int tx = threadIdx.x, ty = threadIdx.y;   // 32 x 8
#pragma unroll
    for (int i = 0; i < 32; i += 8)
        t[ty + i][tx] = W1[(size_t)(k0 + ty + i) * NH + n0 + tx];
    __syncthreads();
#pragma unroll
    for (int i = 0; i < 32; i += 8) {
        float v = t[tx][ty + i];                    // W1[k0+tx][n0+ty+i]
        __nv_bfloat16 hi = __float2bfloat16(v);
        __nv_bfloat16 lo = __float2bfloat16(v - __bfloat162float(hi));
        g_w1t_hi[(size_t)(n0 + ty + i) * ND + k0 + tx] = hi;
        g_w1t_lo[(size_t)(n0 + ty + i) * ND + k0 + tx] = lo;
    }
}

// ============================================================================
// Kernel 0b: bf16-split x -> g_x_hi / g_x_lo  (memory-bound; 8 floats/thread)
// ============================================================================
__global__ void prep_x(const float* __restrict__ x)
{
    size_t i8 = (size_t)blockIdx.x * 256 + threadIdx.x;   // 8-float chunk index
    float4 v0 = ((const float4*)x)[2 * i8];
    float4 v1 = ((const float4*)x)[2 * i8 + 1];
    uint4 hi, lo;
    __nv_bfloat16 h[8], l[8];
    const float f[8] = {v0.x, v0.y, v0.z, v0.w, v1.x, v1.y, v1.z, v1.w};
#pragma unroll
    for (int i = 0; i < 8; i++) {
        h[i] = __float2bfloat16(f[i]);
        l[i] = __float2bfloat16(f[i] - __bfloat162float(h[i]));
    }
    hi.x = ((uint32_t)*(uint16_t*)&h[1] << 16) | *(uint16_t*)&h[0];
    hi.y = ((uint32_t)*(uint16_t*)&h[3] << 16) | *(uint16_t*)&h[2];
    hi.z = ((uint32_t)*(uint16_t*)&h[5] << 16) | *(uint16_t*)&h[4];
    hi.w = ((uint32_t)*(uint16_t*)&h[7] << 16) | *(uint16_t*)&h[6];
    lo.x = ((uint32_t)*(uint16_t*)&l[1] << 16) | *(uint16_t*)&l[0];
    lo.y = ((uint32_t)*(uint16_t*)&l[3] << 16) | *(uint16_t*)&l[2];
    lo.z = ((uint32_t)*(uint16_t*)&l[5] << 16) | *(uint16_t*)&l[4];
    lo.w = ((uint32_t)*(uint16_t*)&l[7] << 16) | *(uint16_t*)&l[6];
    ((uint4*)g_x_hi)[i8] = hi;
    ((uint4*)g_x_lo)[i8] = lo;
}

// ============================================================================
// Kernel 1: split-bf16 wmma GEMM  h = x @ W1  (3 MMAs per fp32 MMA) with fused
//           bias+ReLU+(.W2) epilogue -> g_ypart[nt][batch row].
// CTA: BM=128 batch x BN=128 hidden, BK=32, 8 warps (2m x 4n), warp m64n32.
// Byte-exact R10 mainloop (measured best): 2-stage cp.async, occ 2,
// issue(s+1) -> wait_group 1 -> sync -> compute -> sync.
// ============================================================================
__global__ __launch_bounds__(256, 2) void gemm_mma(
    const float* __restrict__ b1v, const float* __restrict__ W2v)
{
    extern __shared__ __align__(128) char smc[];
    __shared__ float b1s[128], w2s[128];
    __shared__ float red2[256];

    const int tid = threadIdx.x;
    const int wid = tid >> 5;
    const int nt = blockIdx.x;          // 0..3   hidden tile (fast -> x-slice L2 reuse)
    const int mt = blockIdx.y;          // 0..127 batch tile
    const int n0 = nt * 128;
    const int m0 = mt * 128;
    const int wm = wid & 1;             // warp m block (64)
    const int wn = wid >> 1;            // warp n block (32)
    const uint32_t smb = smem_u32(smc);

    if (tid < 128) { b1s[tid] = b1v[n0 + tid]; w2s[tid] = W2v[n0 + tid]; }

    wmma::fragment<wmma::accumulator, 16, 16, 16, float> acc[4][2];
#pragma unroll
    for (int i = 0; i < 4; i++)
#pragma unroll
        for (int j = 0; j < 2; j++) wmma::fill_fragment(acc[i][j], 0.0f);

    // ---- async stage loader: 2048 x 16B chunks per stage, 8 per thread ----
    auto issue = [&](int s) {
        const int buf = s & 1;
        const int k0 = s * 32;
#pragma unroll
        for (int i = 0; i < 8; i++) {
            int ch = tid + 256 * i;
            int isB = ch >> 10;
            int c2 = ch & 1023;
            int split = c2 >> 9;
            int rc = c2 & 511;
            int r = rc >> 2, q = rc & 3;
            const __nv_bfloat16* gbase =
                isB ? (split ? g_w1t_lo : g_w1t_hi) : (split ? g_x_lo : g_x_hi);
            int row0 = isB ? n0 : m0;
            const void* gptr = gbase + (size_t)(row0 + r) * ND + k0 + q * 8;
            uint32_t sptr = smb + (uint32_t)(isB * 49152 + (buf * 2 + split) * TILE_B
                                             + r * 96 + q * 16);
            asm volatile("cp.async.cg.shared.global [%0], [%1], 16;"
                         :: "r"(sptr), "l"(gptr));
        }
        asm volatile("cp.async.commit_group;");
    };

    issue(0);

    for (int s = 0; s < NSTAGE; s++) {
        const int buf = s & 1;
        if (s + 1 < NSTAGE) {
            issue(s + 1);
            asm volatile("cp.async.wait_group 1;");
        } else {
            asm volatile("cp.async.wait_group 0;");
        }
        __syncthreads();

        const __nv_bfloat16* Ah = (const __nv_bfloat16*)(smc + (buf * 2 + 0) * TILE_B);
        const __nv_bfloat16* Al = (const __nv_bfloat16*)(smc + (buf * 2 + 1) * TILE_B);
        const __nv_bfloat16* Bh = (const __nv_bfloat16*)(smc + 49152 + (buf * 2 + 0) * TILE_B);
        const __nv_bfloat16* Bl = (const __nv_bfloat16*)(smc + 49152 + (buf * 2 + 1) * TILE_B);

#pragma unroll
        for (int kk = 0; kk < 2; kk++) {
            wmma::fragment<wmma::matrix_b, 16, 16, 16, __nv_bfloat16, wmma::col_major> bh[2], bl[2];
#pragma unroll
            for (int j = 0; j < 2; j++) {
                wmma::load_matrix_sync(bh[j], Bh + (wn * 32 + 16 * j) * 48 + kk * 16, 48);
                wmma::load_matrix_sync(bl[j], Bl + (wn * 32 + 16 * j) * 48 + kk * 16, 48);
            }
#pragma unroll
            for (int i = 0; i < 4; i++) {
                wmma::fragment<wmma::matrix_a, 16, 16, 16, __nv_bfloat16, wmma::row_major> ah, al;
                wmma::load_matrix_sync(ah, Ah + (wm * 64 + 16 * i) * 48 + kk * 16, 48);
                wmma::load_matrix_sync(al, Al + (wm * 64 + 16 * i) * 48 + kk * 16, 48);
#pragma unroll
                for (int j = 0; j < 2; j++) {
                    wmma::mma_sync(acc[i][j], ah, bh[j], acc[i][j]);
                    wmma::mma_sync(acc[i][j], ah, bl[j], acc[i][j]);
                    wmma::mma_sync(acc[i][j], al, bh[j], acc[i][j]);
                }
            }
        }
        __syncthreads();
    }

    // ---- epilogue: h -> relu(h+b1)*W2, reduce over this CTA's 128 hidden cols
    float* ep = (float*)smc;   // [128][132], aliases stage buffers (loads done)
#pragma unroll
    for (int i = 0; i < 4; i++)
#pragma unroll
        for (int j = 0; j < 2; j++)
            wmma::store_matrix_sync(&ep[(size_t)(wm * 64 + 16 * i) * 132 + wn * 32 + 16 * j],
                                    acc[i][j], 132, wmma::mem_row_major);
    __syncthreads();

    const int row = tid & 127;
    const int half = tid >> 7;
    float p = 0.f;
#pragma unroll 8
    for (int n = half * 64; n < half * 64 + 64; n++)
        p += fmaxf(ep[(size_t)row * 132 + n] + b1s[n], 0.f) * w2s[n];
    red2[tid] = p;
    __syncthreads();
    if (tid < 128)
        g_ypart[(size_t)nt * NB + m0 + tid] = red2[tid] + red2[tid + 128];
}

// ============================================================================
// Kernel 2: fused predictor tail + exact per-row k-th-smallest |x| radix
// select + mask / sparse_x / actual_sparsity / l1. One 256t CTA per row.
// R13 version (measured best): 40 regs, occ 6.
// ============================================================================
__global__ __launch_bounds__(256, 6) void select_mask(
    const float* __restrict__ x, const float* __restrict__ b2,
    float* __restrict__ out)
{
    __shared__ unsigned hist[2048];
    __shared__ unsigned buf[2048];
    __shared__ unsigned wsum[8];
    __shared__ float    fred[256];
    __shared__ unsigned sh_sel, sh_rem, sh_cnt, sh_thr, sh_k;

    const int t = threadIdx.x;
    const int lane = t & 31;
    const int warp = t >> 5;
    const int r = blockIdx.x;
    const float4* xrow = (const float4*)(x + (size_t)r * ND);

    // --- fused predictor tail (thread 0) ---
    if (t == 0) {
        float y = ((g_ypart[r] + g_ypart[NB + r])
                   + (g_ypart[2 * NB + r] + g_ypart[3 * NB + r])) + b2[0];
        float sig = 1.f / (1.f + expf(-y));
        float s = 0.05f + 0.25f * sig;
        out[(size_t)2 * NB * ND + r] = s;                 // sparsity
        float kf = rintf(2048.0f * (1.0f - s));           // half-even, matches jnp.round
        int k = (int)kf;
        if (k < 1) k = 1;
        sh_k = (unsigned)k;
        sh_cnt = 0u;
    }

    float4 xv0 = xrow[t];
    float4 xv1 = xrow[t + 256];
    unsigned u0[4], u1[4];
    u0[0] = __float_as_uint(xv0.x) & 0x7fffffffu;
    u0[1] = __float_as_uint(xv0.y) & 0x7fffffffu;
    u0[2] = __float_as_uint(xv0.z) & 0x7fffffffu;
    u0[3] = __float_as_uint(xv0.w) & 0x7fffffffu;
    u1[0] = __float_as_uint(xv1.x) & 0x7fffffffu;
    u1[1] = __float_as_uint(xv1.y) & 0x7fffffffu;
    u1[2] = __float_as_uint(xv1.z) & 0x7fffffffu;
    u1[3] = __float_as_uint(xv1.w) & 0x7fffffffu;
#pragma unroll
    for (int i = 0; i < 8; i++) hist[t + 256 * i] = 0u;
    __syncthreads();

#pragma unroll
    for (int i = 0; i < 4; i++) atomicAdd(&hist[u0[i] >> 20], 1u);
#pragma unroll
    for (int i = 0; i < 4; i++) atomicAdd(&hist[u1[i] >> 20], 1u);
    __syncthreads();

    const unsigned k = sh_k;

    // Shuffle-based segmented scan over bin sums; thread t owns bins [8t, 8t+8)
    unsigned ssum = 0u;
#pragma unroll
    for (int i = 0; i < 8; i++) ssum += hist[8 * t + i];
    unsigned v = ssum;
#pragma unroll
    for (int off = 1; off < 32; off <<= 1) {
        unsigned n = __shfl_up_sync(0xffffffffu, v, off);
        if (lane >= off) v += n;
    }
    if (lane == 31) wsum[warp] = v;
    __syncthreads();
    unsigned wexcl = 0u;
#pragma unroll
    for (int w = 0; w < 8; w++) wexcl += (w < warp) ? wsum[w] : 0u;
    unsigned incl = wexcl + v;
    unsigned excl = incl - ssum;
    if (excl < k && k <= incl) {
        unsigned c = excl;
        for (int i = 0; i < 8; i++) {       // winner re-reads its bins from smem
            unsigned hc = hist[8 * t + i];
            c += hc;
            if (c >= k) { sh_sel = 8 * t + i; sh_rem = k - (c - hc); break; }
        }
    }
    __syncthreads();
    const unsigned sel = sh_sel;
    const unsigned rem = sh_rem;        // rank of threshold inside candidate bin
    const unsigned binexcl = k - rem;   // elements strictly below the bin

    // Warp-aggregated candidate compaction (buf order irrelevant for rank select)
    unsigned mv[8];
    unsigned nm = 0;
#pragma unroll
    for (int i = 0; i < 4; i++) if ((u0[i] >> 20) == sel) mv[nm++] = u0[i];
#pragma unroll
    for (int i = 0; i < 4; i++) if ((u1[i] >> 20) == sel) mv[nm++] = u1[i];
    unsigned v2 = nm;
#pragma unroll
    for (int off = 1; off < 32; off <<= 1) {
        unsigned n = __shfl_up_sync(0xffffffffu, v2, off);
        if (lane >= off) v2 += n;
    }
    unsigned wtot = __shfl_sync(0xffffffffu, v2, 31);
    unsigned wbase = 0;
    if (lane == 31 && wtot > 0) wbase = atomicAdd(&sh_cnt, wtot);
    wbase = __shfl_sync(0xffffffffu, wbase, 31);
    unsigned base = wbase + v2 - nm;
    for (unsigned j = 0; j < nm; j++) buf[base + j] = mv[j];
    __syncthreads();
    const int m = (int)sh_cnt;

    // Exact rank select among m candidates (rem-th smallest), tie-safe.
    // Winner also derives actual_sparsity: count_le = binexcl + less + eq.
    for (int c = t; c < m; c += 256) {
        unsigned vv = buf[c];
        unsigned less = 0u, eq = 0u;
        for (int j = 0; j < m; j++) {
            unsigned w = buf[j];
            less += (w < vv);
            eq   += (w == vv);
        }
        if (less < rem && rem <= less + eq) {
            sh_thr = vv;   // unique value among writers
            out[(size_t)2 * NB * ND + NB + r] =
                (float)(2048u - (binexcl + less + eq)) * (1.f / 2048.f);
        }
    }
    __syncthreads();
    const unsigned thr = sh_thr;   // exact bit pattern of sorted_abs[k-1]

    // Outputs: sparse_x, mask (strict > threshold), l1 (from abs bit patterns)
    float4* sp = (float4*)(out + (size_t)r * ND);
    float4* mk = (float4*)(out + (size_t)NB * ND + (size_t)r * ND);
    float l1 = 0.f;
    {
        float4 spv, mkv;
        bool k0b = u0[0] > thr, k1b = u0[1] > thr, k2b = u0[2] > thr, k3b = u0[3] > thr;
        spv.x = k0b ? xv0.x : 0.f; mkv.x = k0b ? 1.f : 0.f;
        spv.y = k1b ? xv0.y : 0.f; mkv.y = k1b ? 1.f : 0.f;
        spv.z = k2b ? xv0.z : 0.f; mkv.z = k2b ? 1.f : 0.f;
        spv.w = k3b ? xv0.w : 0.f; mkv.w = k3b ? 1.f : 0.f;
        l1 += __uint_as_float(k0b ? u0[0] : 0u) + __uint_as_float(k1b ? u0[1] : 0u)
            + __uint_as_float(k2b ? u0[2] : 0u) + __uint_as_float(k3b ? u0[3] : 0u);
        sp[t] = spv; mk[t] = mkv;

        k0b = u1[0] > thr; k1b = u1[1] > thr; k2b = u1[2] > thr; k3b = u1[3] > thr;
        spv.x = k0b ? xv1.x : 0.f; mkv.x = k0b ? 1.f : 0.f;
        spv.y = k1b ? xv1.y : 0.f; mkv.y = k1b ? 1.f : 0.f;
        spv.z = k2b ? xv1.z : 0.f; mkv.z = k2b ? 1.f : 0.f;
        spv.w = k3b ? xv1.w : 0.f; mkv.w = k3b ? 1.f : 0.f;
        l1 += __uint_as_float(k0b ? u1[0] : 0u) + __uint_as_float(k1b ? u1[1] : 0u)
            + __uint_as_float(k2b ? u1[2] : 0u) + __uint_as_float(k3b ? u1[3] : 0u);
        sp[t + 256] = spv; mk[t + 256] = mkv;
    }

    fred[t] = l1;
    __syncthreads();
    for (int off = 128; off > 0; off >>= 1) {
        if (t < off) fred[t] += fred[t + off];
        __syncthreads();
    }
    if (t == 0) g_l1[r] = fred[0];
}

// ============================================================================
// Kernel 3: deterministic mean of per-row l1 sums -> l1_reg scalar
// ============================================================================
__global__ void l1_reduce(float* __restrict__ out)
{
    __shared__ float sm[1024];
    int t = threadIdx.x;
    float s = 0.f;
    for (int i = t; i < NB; i += 1024) s += g_l1[i];
    sm[t] = s;
    __syncthreads();
    for (int off = 512; off > 0; off >>= 1) {
        if (t < off) sm[t] += sm[t + off];
        __syncthreads();
    }
    if (t == 0) out[(size_t)2 * NB * ND + 2 * NB] = sm[0] * (1.f / (float)NB);
}

// ============================================================================
extern "C" void kernel_launch(void* const* d_in, const int* in_sizes, int n_in,
                              void* d_out, int out_size)
{
    const float* x  = (const float*)d_in[0];
    const float* W1 = (const float*)d_in[1];
    const float* b1 = (const float*)d_in[2];
    const float* W2 = (const float*)d_in[3];
    const float* b2 = (const float*)d_in[4];
    float* out = (float*)d_out;

    cudaFuncSetAttribute(gemm_mma, cudaFuncAttributeMaxDynamicSharedMemorySize, SMEM_DYN);

    prep_w1t<<<dim3(ND / 32, NH / 32), dim3(32, 8)>>>(W1);
    prep_x<<<(int)((size_t)NB * ND / 8 / 256), 256>>>(x);
    gemm_mma<<<dim3(4, NB / 128), 256, SMEM_DYN>>>(b1, W2);
    select_mask<<<NB, 256>>>(x, b2, out);
    l1_reduce<<<1, 1024>>>(out);
}